// round 11
// baseline (speedup 1.0000x reference)
#include <cuda_runtime.h>
#include <cuda_bf16.h>
#include <cstdint>
#include <cstddef>

// Problem dims
#define B_ 8
#define L_ 1024
#define N_ 4096
#define D_ 1024
#define SCALE_F 0.03125f   // 1/sqrt(1024)/TEMPERATURE

// GEMM tiling: 128x128 tile, BK=32 (64B bf16 rows, SW64-style swizzle)
#define BM 128
#define BN 128
#define BK 32
#define KSTEPS (D_ / BK)              // 32
#define NTILES (N_ / BN)              // 32

// NOTE: deliberately ZERO module-scope __device__ data. All cross-kernel
// state lives in d_out; all per-tile state lives in static shared memory.

// ---------------- PTX helpers (base ISA only) ----------------
__device__ __forceinline__ uint32_t smem_u32(const void* p) {
    uint32_t a;
    asm("{ .reg .u64 t; cvta.to.shared.u64 t, %1; cvt.u32.u64 %0, t; }"
        : "=r"(a) : "l"(p));
    return a;
}

__device__ __forceinline__ void sts8(uint32_t addr, uint32_t u0, uint32_t u1) {
    asm volatile("st.shared.v2.b32 [%0], {%1,%2};" :: "r"(addr), "r"(u0), "r"(u1));
}

__device__ __forceinline__ void ldsm4(uint32_t* r, uint32_t addr) {
    asm volatile("ldmatrix.sync.aligned.m8n8.x4.shared.b16 {%0,%1,%2,%3}, [%4];"
                 : "=r"(r[0]), "=r"(r[1]), "=r"(r[2]), "=r"(r[3]) : "r"(addr));
}

__device__ __forceinline__ void mma16816(float* c, const uint32_t* a, const uint32_t* b) {
    asm volatile(
        "mma.sync.aligned.m16n8k16.row.col.f32.bf16.bf16.f32 "
        "{%0,%1,%2,%3}, {%4,%5,%6,%7}, {%8,%9}, {%0,%1,%2,%3};"
        : "+f"(c[0]), "+f"(c[1]), "+f"(c[2]), "+f"(c[3])
        : "r"(a[0]), "r"(a[1]), "r"(a[2]), "r"(a[3]), "r"(b[0]), "r"(b[1]));
}

// ============================================================================
// Kernel 1: zero the s_ia output region (d_out is poisoned to 0xAA).
// ============================================================================
__global__ void __launch_bounds__(256) zero_sia_kernel(float* __restrict__ out) {
    int idx = blockIdx.x * 256 + threadIdx.x;
    if (idx < B_ * N_) out[idx] = 0.0f;
}

// ============================================================================
// Kernel 2: fused GEMM + norm + exp, with ZERO global scratch.
// Bilinearity: logits = (a.b) * rinvA * rinvB * scale, so the MMA runs on RAW
// bf16-converted inputs; inverse norms are computed in-kernel (loader threads
// stream entire rows, accumulating sum-of-squares during conversion) and
// applied in the epilogue before exp. |logit| <= 1/32 -> exp safe, no max.
// Static smem only: 2-stage bf16 buffers (32 KB) + 1 KB rinv publish.
// 8 warps: 4(M) x 2(N); warp tile 32x64.
// ============================================================================
__global__ void __launch_bounds__(256) gemm_exp_kernel(
    float* __restrict__ outA,
    const float4* __restrict__ text, const float4* __restrict__ visual) {
    __shared__ __align__(128) __nv_bfloat16 smA[2][BM * BK];   // 2 x 8 KB
    __shared__ __align__(128) __nv_bfloat16 smB[2][BN * BK];   // 2 x 8 KB
    __shared__ float sRA[BM];                                  // rinvA per tile row
    __shared__ float sRB[BN];                                  // rinvB per tile col
    const uint32_t aBuf0 = smem_u32(&smA[0][0]);
    const uint32_t aBuf1 = smem_u32(&smA[1][0]);
    const uint32_t bBuf0 = smem_u32(&smB[0][0]);
    const uint32_t bBuf1 = smem_u32(&smB[1][0]);

    const int tid = threadIdx.x;
    const int wid = tid >> 5, lane = tid & 31;
    const int nt = blockIdx.x, mt = blockIdx.y, b = blockIdx.z;
    const int m0 = mt * BM, n0 = nt * BN;
    const int wm = (wid & 3) * 32;
    const int wnIdx = wid >> 2;
    const int wn = wnIdx * 64;

    // loader mapping: 2 threads per row; each owns 16 floats (4 float4) per k-step
    const int lrow = tid >> 1;            // 0..127
    const int h    = tid & 1;             // half of the BK=32 slice
    const float4* gA = text   + ((size_t)(b * L_ + m0 + lrow)) * 256 + h * 4;
    const float4* gB = visual + ((size_t)(b * N_ + n0 + lrow)) * 256 + h * 4;
    const uint32_t stRow = (uint32_t)lrow * 64;
    const uint32_t stSw  = (uint32_t)((lrow >> 1) & 3) * 16;

    float c[2][8][4];
#pragma unroll
    for (int t = 0; t < 2; t++)
#pragma unroll
        for (int n = 0; n < 8; n++)
#pragma unroll
            for (int j = 0; j < 4; j++) c[t][n][j] = 0.0f;

    float ssA = 0.0f, ssB = 0.0f;         // row sum-of-squares (this thread's half)
    float4 ra[4], rb[4];
    // prefetch + convert stage 0 (raw values; accumulate sumsq)
#pragma unroll
    for (int i = 0; i < 4; i++) { ra[i] = gA[i]; rb[i] = gB[i]; }
#pragma unroll
    for (int i = 0; i < 4; i++) {
        ssA += ra[i].x * ra[i].x + ra[i].y * ra[i].y + ra[i].z * ra[i].z + ra[i].w * ra[i].w;
        ssB += rb[i].x * rb[i].x + rb[i].y * rb[i].y + rb[i].z * rb[i].z + rb[i].w * rb[i].w;
        const uint32_t off = stRow + (((uint32_t)(h * 32 + i * 8)) ^ stSw);
        __nv_bfloat162 p0 = __float22bfloat162_rn(make_float2(ra[i].x, ra[i].y));
        __nv_bfloat162 p1 = __float22bfloat162_rn(make_float2(ra[i].z, ra[i].w));
        sts8(aBuf0 + off, *reinterpret_cast<uint32_t*>(&p0), *reinterpret_cast<uint32_t*>(&p1));
        p0 = __float22bfloat162_rn(make_float2(rb[i].x, rb[i].y));
        p1 = __float22bfloat162_rn(make_float2(rb[i].z, rb[i].w));
        sts8(bBuf0 + off, *reinterpret_cast<uint32_t*>(&p0), *reinterpret_cast<uint32_t*>(&p1));
    }
    __syncthreads();

    // per-lane ldmatrix constants (64B rows)
    const int aRow = wm + (lane & 15);
    const int aGh  = lane >> 4;
    const int bRow = wn + (lane & 7) + ((lane >> 4) << 3);
    const int bGh  = (lane >> 3) & 1;
    const uint32_t aOff = (uint32_t)aRow * 64;
    const uint32_t aSw  = (uint32_t)((aRow >> 1) & 3) * 16;
    const uint32_t bOff = (uint32_t)bRow * 64;
    const uint32_t bSw  = (uint32_t)((bRow >> 1) & 3) * 16;

    for (int ks = 0; ks < KSTEPS; ks++) {
        // prefetch next stage's fp32 (hidden by MMAs below) + accumulate sumsq
        if (ks + 1 < KSTEPS) {
            const int kf = (ks + 1) * 8;          // float4 offset within row
#pragma unroll
            for (int i = 0; i < 4; i++) { ra[i] = gA[kf + i]; rb[i] = gB[kf + i]; }
#pragma unroll
            for (int i = 0; i < 4; i++) {
                ssA += ra[i].x * ra[i].x + ra[i].y * ra[i].y + ra[i].z * ra[i].z + ra[i].w * ra[i].w;
                ssB += rb[i].x * rb[i].x + rb[i].y * rb[i].y + rb[i].z * rb[i].z + rb[i].w * rb[i].w;
            }
        }

        // ---- MMA over current bf16 buffers (BK=32 -> 2 k16 steps) ----
        const uint32_t aB = (ks & 1) ? aBuf1 : aBuf0;
        const uint32_t bB = (ks & 1) ? bBuf1 : bBuf0;
#pragma unroll
        for (int q = 0; q < 2; q++) {
            const uint32_t aC = (uint32_t)((2 * q + aGh) * 16) ^ aSw;
            const uint32_t bC = (uint32_t)((2 * q + bGh) * 16) ^ bSw;
            uint32_t afr0[4], afr1[4];
            ldsm4(afr0, aB + aOff + aC);
            ldsm4(afr1, aB + aOff + 16 * 64 + aC);
#pragma unroll
            for (int i = 0; i < 4; i++) {
                uint32_t bfr[4];
                ldsm4(bfr, bB + bOff + i * (16 * 64) + bC);
                mma16816(c[0][2 * i + 0], afr0, &bfr[0]);
                mma16816(c[0][2 * i + 1], afr0, &bfr[2]);
                mma16816(c[1][2 * i + 0], afr1, &bfr[0]);
                mma16816(c[1][2 * i + 1], afr1, &bfr[2]);
            }
        }

        // ---- convert + store next stage, then sync ----
        if (ks + 1 < KSTEPS) {
            const uint32_t na = (ks & 1) ? aBuf0 : aBuf1;
            const uint32_t nb = (ks & 1) ? bBuf0 : bBuf1;
#pragma unroll
            for (int i = 0; i < 4; i++) {
                const uint32_t off = stRow + (((uint32_t)(h * 32 + i * 8)) ^ stSw);
                __nv_bfloat162 p0 = __float22bfloat162_rn(make_float2(ra[i].x, ra[i].y));
                __nv_bfloat162 p1 = __float22bfloat162_rn(make_float2(ra[i].z, ra[i].w));
                sts8(na + off, *reinterpret_cast<uint32_t*>(&p0), *reinterpret_cast<uint32_t*>(&p1));
                p0 = __float22bfloat162_rn(make_float2(rb[i].x, rb[i].y));
                p1 = __float22bfloat162_rn(make_float2(rb[i].z, rb[i].w));
                sts8(nb + off, *reinterpret_cast<uint32_t*>(&p0), *reinterpret_cast<uint32_t*>(&p1));
            }
            __syncthreads();
        }
    }

    // ---- publish inverse norms (pair lanes 2r/2r+1 hold the two row halves) ----
    ssA += __shfl_xor_sync(0xFFFFFFFFu, ssA, 1);
    ssB += __shfl_xor_sync(0xFFFFFFFFu, ssB, 1);
    if (h == 0) {
        sRA[lrow] = SCALE_F / fmaxf(sqrtf(ssA), 1e-12f);
        sRB[lrow] = 1.0f / fmaxf(sqrtf(ssB), 1e-12f);
    }
    __syncthreads();

    // ---------------- epilogue: scale by rinvA*rinvB, exp, store E ------------
    const int qrow = lane >> 2;
    const int qcol = lane & 3;
#pragma unroll
    for (int t = 0; t < 2; t++) {
        const int row = wm + t * 16 + qrow;
        const float ra0 = sRA[row];
        const float ra1 = sRA[row + 8];
        float* o0 = outA + ((size_t)b * L_ + (m0 + row)) * N_ + (n0 + wn + 2 * qcol);
#pragma unroll
        for (int n = 0; n < 8; n++) {
            const int col = wn + n * 8 + 2 * qcol;
            const float rb0 = sRB[col];
            const float rb1 = sRB[col + 1];
            float e0 = __expf(c[t][n][0] * ra0 * rb0);
            float e1 = __expf(c[t][n][1] * ra0 * rb1);
            float e2 = __expf(c[t][n][2] * ra1 * rb0);
            float e3 = __expf(c[t][n][3] * ra1 * rb1);
            reinterpret_cast<float2*>(o0 + n * 8)[0] = make_float2(e0, e1);
            reinterpret_cast<float2*>(o0 + 8 * N_ + n * 8)[0] = make_float2(e2, e3);
        }
    }
}

// ============================================================================
// Kernel 3: finalize. Block = (8-row L-chunk, batch). Recomputes the beta
// normalizer (4 KB read), computes 8 row-sums of E (one warp per row),
// scales A = E * inv in place, and atomically accumulates
// s_ia[b,n] += sum_l w_l * A[l,n] into the (pre-zeroed) s_ia region.
// ============================================================================
__global__ void __launch_bounds__(256) finalize_kernel(
    float* __restrict__ outA, float* __restrict__ out_sia,
    const float* __restrict__ beta, const int* __restrict__ mask) {
    __shared__ float red[8];
    __shared__ float s_inv[8], s_w[8];
    const int b = blockIdx.y;
    const int chunk = blockIdx.x;            // 0..127 (8 rows each)
    const int tid = threadIdx.x;
    const int lane = tid & 31, w = tid >> 5; // 8 warps

    // beta normalizer: sum over beta*mask for this batch
    float bs = 0.0f;
#pragma unroll
    for (int i = 0; i < 4; i++) {
        int l = tid + i * 256;
        bs += beta[b * L_ + l] * (mask[b * L_ + l] != 0 ? 1.0f : 0.0f);
    }
#pragma unroll
    for (int o = 16; o > 0; o >>= 1) bs += __shfl_xor_sync(0xFFFFFFFFu, bs, o);
    if (lane == 0) red[w] = bs;
    __syncthreads();
    const float bdsum = red[0] + red[1] + red[2] + red[3]
                      + red[4] + red[5] + red[6] + red[7];

    // row sums: warp w handles row l = chunk*8 + w
    const int l = chunk * 8 + w;
    const float4* ep = (const float4*)(outA + ((size_t)b * L_ + l) * N_);
    float rs = 0.0f;
#pragma unroll 4
    for (int i = lane; i < N_ / 4; i += 32) {
        float4 v = ep[i];
        rs += (v.x + v.y) + (v.z + v.w);
    }
#pragma unroll
    for (int o = 16; o > 0; o >>= 1) rs += __shfl_xor_sync(0xFFFFFFFFu, rs, o);
    if (lane == 0) {
        const float m = (mask[b * L_ + l] != 0) ? 1.0f : 0.0f;
        s_inv[w] = (m != 0.0f) ? (1.0f / rs) : 0.0f;
        s_w[w]   = beta[b * L_ + l] * m / (bdsum + 1e-8f);
    }
    __syncthreads();

    // scale + accumulate: thread owns float4s at {tid, tid+256, tid+512, tid+768}
    float4 acc0 = make_float4(0.f, 0.f, 0.f, 0.f);
    float4 acc1 = acc0, acc2 = acc0, acc3 = acc0;
#pragma unroll
    for (int r = 0; r < 8; r++) {
        const float iv = s_inv[r];
        const float wt = s_w[r];
        float4* row = (float4*)(outA + ((size_t)b * L_ + chunk * 8 + r) * N_);
        float4 e0 = row[tid];
        float4 e1 = row[tid + 256];
        float4 e2 = row[tid + 512];
        float4 e3 = row[tid + 768];
        e0.x *= iv; e0.y *= iv; e0.z *= iv; e0.w *= iv;
        e1.x *= iv; e1.y *= iv; e1.z *= iv; e1.w *= iv;
        e2.x *= iv; e2.y *= iv; e2.z *= iv; e2.w *= iv;
        e3.x *= iv; e3.y *= iv; e3.z *= iv; e3.w *= iv;
        row[tid] = e0; row[tid + 256] = e1; row[tid + 512] = e2; row[tid + 768] = e3;
        acc0.x += wt * e0.x; acc0.y += wt * e0.y; acc0.z += wt * e0.z; acc0.w += wt * e0.w;
        acc1.x += wt * e1.x; acc1.y += wt * e1.y; acc1.z += wt * e1.z; acc1.w += wt * e1.w;
        acc2.x += wt * e2.x; acc2.y += wt * e2.y; acc2.z += wt * e2.z; acc2.w += wt * e2.w;
        acc3.x += wt * e3.x; acc3.y += wt * e3.y; acc3.z += wt * e3.z; acc3.w += wt * e3.w;
    }
    float* sb = out_sia + b * N_;
    atomicAdd(sb + (tid)       * 4 + 0, acc0.x);
    atomicAdd(sb + (tid)       * 4 + 1, acc0.y);
    atomicAdd(sb + (tid)       * 4 + 2, acc0.z);
    atomicAdd(sb + (tid)       * 4 + 3, acc0.w);
    atomicAdd(sb + (tid + 256) * 4 + 0, acc1.x);
    atomicAdd(sb + (tid + 256) * 4 + 1, acc1.y);
    atomicAdd(sb + (tid + 256) * 4 + 2, acc1.z);
    atomicAdd(sb + (tid + 256) * 4 + 3, acc1.w);
    atomicAdd(sb + (tid + 512) * 4 + 0, acc2.x);
    atomicAdd(sb + (tid + 512) * 4 + 1, acc2.y);
    atomicAdd(sb + (tid + 512) * 4 + 2, acc2.z);
    atomicAdd(sb + (tid + 512) * 4 + 3, acc2.w);
    atomicAdd(sb + (tid + 768) * 4 + 0, acc3.x);
    atomicAdd(sb + (tid + 768) * 4 + 1, acc3.y);
    atomicAdd(sb + (tid + 768) * 4 + 2, acc3.z);
    atomicAdd(sb + (tid + 768) * 4 + 3, acc3.w);
}

// ============================================================================
extern "C" void kernel_launch(void* const* d_in, const int* in_sizes, int n_in,
                              void* d_out, int out_size) {
    const float* text = (const float*)d_in[0];
    const float* vis  = (const float*)d_in[1];
    const float* beta = (const float*)d_in[2];
    const int*   mask = (const int*)d_in[3];
    float* out  = (float*)d_out;
    float* outA = out + B_ * N_;   // s_ia first, then A

    zero_sia_kernel<<<(B_ * N_ + 255) / 256, 256>>>(out);
    gemm_exp_kernel<<<dim3(NTILES, L_ / BM, B_), 256>>>(
        outA, (const float4*)text, (const float4*)vis);
    finalize_kernel<<<dim3(L_ / 8, B_), 256>>>(outA, out, beta, mask);
}